// round 17
// baseline (speedup 1.0000x reference)
#include <cuda_runtime.h>
#include <cuda_fp16.h>
#include <cstdint>
#include <cstddef>

#define DM 1024
#define NH 16
#define DK 64
#define BB 2
#define SSEQ 2048
#define MTOT (BB*SSEQ)     // 4096
#define BH (BB*NH)         // 32

#define EXPC 0.18033688011112042f   // 0.125 * log2(e)

// Packed half2 words (uint32), k/d sigma-paired within 8-word (16-half) groups.
__device__ uint32_t g_Qh[(size_t)MTOT*512];
__device__ uint32_t g_Kh[(size_t)MTOT*512];
__device__ uint32_t g_Vh[(size_t)MTOT*512];
__device__ uint32_t g_Wh[4][(size_t)DM*512];
__device__ uint32_t g_q[(size_t)BH*SSEQ*32];   // projected q [bh][s][32w]
__device__ uint32_t g_k[(size_t)BH*SSEQ*32];
__device__ uint32_t g_vT[(size_t)BH*DK*1024];  // [bh][64 d][1024w keys sigma'd]
__device__ uint32_t g_attnh[(size_t)MTOT*512]; // merged attn, packed
__device__ uint32_t g_mbits[(size_t)BB*SSEQ*(SSEQ/32)];
__device__ uint32_t g_exph[(size_t)BH*SSEQ*1024];  // half2 exp(scores), 268 MB

// ---------------------------------------------------------------------------
__device__ __forceinline__ uint32_t h2pack(float a, float b) {
    __half2 h = __floats2half2_rn(a, b);
    return *(uint32_t*)&h;
}
__device__ __forceinline__ void mma_f16(float* c, const uint32_t* a, const uint32_t* b) {
    asm volatile(
        "mma.sync.aligned.m16n8k16.row.col.f32.f16.f16.f32 "
        "{%0,%1,%2,%3}, {%4,%5,%6,%7}, {%8,%9}, {%0,%1,%2,%3};\n"
        : "+f"(c[0]), "+f"(c[1]), "+f"(c[2]), "+f"(c[3])
        : "r"(a[0]), "r"(a[1]), "r"(a[2]), "r"(a[3]), "r"(b[0]), "r"(b[1]));
}
__device__ __forceinline__ void cp16(uint32_t d, const void* s) {
    asm volatile("cp.async.ca.shared.global [%0], [%1], 16;\n" :: "r"(d), "l"(s));
}
__device__ __forceinline__ void cp_commit() { asm volatile("cp.async.commit_group;\n"); }
template<int N> __device__ __forceinline__ void cp_wait() {
    asm volatile("cp.async.wait_group %0;\n" :: "n"(N));
}
__device__ __host__ __forceinline__ int sigma8(int j) {
    return (j < 4) ? 2 * j : 2 * (j - 4) + 1;
}

// ---------------------------------------------------------------------------
// pack_all: blocks [0,4096) pack Q,K,V,W*; blocks [4096,5120) build maskbits.
// ---------------------------------------------------------------------------
__global__ void pack_all(const float* __restrict__ Q, const float* __restrict__ K,
                         const float* __restrict__ V, const float* __restrict__ WQ,
                         const float* __restrict__ WK, const float* __restrict__ WV,
                         const float* __restrict__ Wo, const unsigned char* __restrict__ mask)
{
    const int blk = blockIdx.x;
    if (blk >= 4096) {
        const int idx = (blk - 4096) * 256 + threadIdx.x;
        const uint32_t* src = (const uint32_t*)(mask + (size_t)idx * 32);
        uint32_t w = 0;
#pragma unroll
        for (int q = 0; q < 8; q++) {
            const uint32_t v = src[q];
            if (v & 0x000000ffu) w |= 1u << (q * 4 + 0);
            if (v & 0x0000ff00u) w |= 1u << (q * 4 + 1);
            if (v & 0x00ff0000u) w |= 1u << (q * 4 + 2);
            if (v & 0xff000000u) w |= 1u << (q * 4 + 3);
        }
        g_mbits[idx] = w;
        return;
    }
    const float* src; uint32_t* dst; int base;
    if      (blk < 1024) { src = Q;  dst = g_Qh;    base = blk; }
    else if (blk < 2048) { src = K;  dst = g_Kh;    base = blk - 1024; }
    else if (blk < 3072) { src = V;  dst = g_Vh;    base = blk - 2048; }
    else if (blk < 3328) { src = WQ; dst = g_Wh[0]; base = blk - 3072; }
    else if (blk < 3584) { src = WK; dst = g_Wh[1]; base = blk - 3328; }
    else if (blk < 3840) { src = WV; dst = g_Wh[2]; base = blk - 3584; }
    else                 { src = Wo; dst = g_Wh[3]; base = blk - 3840; }
    const int idx = base * 256 + threadIdx.x;
    const float* s = src + (size_t)idx * 16;
    uint32_t w[8];
#pragma unroll
    for (int j = 0; j < 8; j++) {
        const float2 v = *(const float2*)(s + 2 * j);
        w[j] = h2pack(v.x, v.y);
    }
    uint4* d = (uint4*)(dst + (size_t)idx * 8);
    d[0] = make_uint4(w[0], w[4], w[1], w[5]);
    d[1] = make_uint4(w[2], w[6], w[3], w[7]);
}

// ---------------------------------------------------------------------------
// Projection GEMM: M=256 x N=128 tile, 512 threads (16 warps = 8m x 2n).
// ---------------------------------------------------------------------------
#define PW 20
#define PJ_SMEM_W 15360
#define PJ_SMEM_BYTES (PJ_SMEM_W*4)

__device__ __forceinline__ void proj_body(
    const uint32_t* __restrict__ Ah, const uint32_t* __restrict__ Wh,
    const float* __restrict__ bias, void* __restrict__ outv, int mode)
{
    extern __shared__ uint32_t psm[];
    const int tid = threadIdx.x;
    const int m0 = blockIdx.y * 256, n0 = blockIdx.x * 128;
    const int lane = tid & 31, warp = tid >> 5;
    const int wm = (warp & 7) * 32, wn = (warp >> 3) * 64;
    const int g = lane >> 2, t = lane & 3;

    const uint32_t sbase = (uint32_t)__cvta_generic_to_shared(psm);
    const int arow = tid >> 1, ae = tid & 1;
    const uint32_t* Asrc = Ah + (size_t)(m0 + arow) * 512 + ae * 8;
    const uint32_t dAb = sbase + (uint32_t)(arow * PW + ae * 8) * 4;
    const int brow = tid >> 2, bseg = tid & 3;
    const uint32_t* Wsrc = Wh + (size_t)(n0 + brow) * 512 + bseg * 4;
    const uint32_t dBb = sbase + (uint32_t)(10240 + brow * PW + bseg * 4) * 4;

    auto stage = [&](int tile, int buf) {
        const uint32_t aoff = (uint32_t)(buf * 5120) * 4;
        const uint32_t boff = (uint32_t)(buf * 2560) * 4;
        cp16(dAb + aoff, Asrc + tile * 16);
        cp16(dAb + aoff + 16, Asrc + tile * 16 + 4);
        cp16(dBb + boff, Wsrc + tile * 16);
    };

    float c[2][8][4] = {};

    stage(0, 0); cp_commit();
    for (int tl = 0; tl < 32; tl++) {
        cp_wait<0>();
        __syncthreads();
        if (tl + 1 < 32) { stage(tl + 1, (tl + 1) & 1); cp_commit(); }
        const uint32_t* As = psm + (tl & 1) * 5120;
        const uint32_t* Bs = psm + 10240 + (tl & 1) * 2560;
#pragma unroll
        for (int ks = 0; ks < 2; ks++) {
            const int kb = ks * 8 + 2 * t;
            uint32_t af[2][4], bf[8][2];
#pragma unroll
            for (int mi = 0; mi < 2; mi++) {
                const int r = wm + mi * 16 + g;
                const uint2 x = *(const uint2*)&As[r * PW + kb];
                const uint2 y = *(const uint2*)&As[(r + 8) * PW + kb];
                af[mi][0] = x.x; af[mi][2] = x.y;
                af[mi][1] = y.x; af[mi][3] = y.y;
            }
#pragma unroll
            for (int ni = 0; ni < 8; ni++) {
                const uint2 z = *(const uint2*)&Bs[(wn + ni * 8 + g) * PW + kb];
                bf[ni][0] = z.x; bf[ni][1] = z.y;
            }
#pragma unroll
            for (int mi = 0; mi < 2; mi++)
#pragma unroll
                for (int ni = 0; ni < 8; ni++)
                    mma_f16(c[mi][ni], af[mi], bf[ni]);
        }
        __syncthreads();
    }

#pragma unroll
    for (int mi = 0; mi < 2; mi++) {
#pragma unroll
        for (int rr = 0; rr < 2; rr++) {
            const int m = m0 + wm + mi * 16 + g + rr * 8;
            const int b_ = m >> 11, s = m & 2047;
#pragma unroll
            for (int ni = 0; ni < 8; ni++) {
                const int n = n0 + wn + ni * 8 + 2 * t;
                const float v0 = c[mi][ni][rr * 2 + 0] + bias[n];
                const float v1 = c[mi][ni][rr * 2 + 1] + bias[n + 1];
                if (mode == 0) {
                    *(float2*)&((float*)outv)[(size_t)m * 1024 + n] = make_float2(v0, v1);
                } else if (mode == 1) {
                    const int h = n >> 6;
                    const int ni_l = (n & 63) >> 3;
                    const int widx = (ni_l >> 1) * 8 + 2 * t + (ni_l & 1);
                    ((uint32_t*)outv)[((size_t)(b_ * 16 + h) * 2048 + s) * 32 + widx] =
                        h2pack(v0, v1);
                } else {
                    const int h = n >> 6;
                    const int dn = n & 63;
                    const int sw = (s >> 4) * 16 + sigma8((s & 15) >> 1) * 2 + (s & 1);
                    __half* vh = (__half*)outv;
                    vh[((size_t)(b_ * 16 + h) * 64 + dn) * 2048 + sw]     = __float2half_rn(v0);
                    vh[((size_t)(b_ * 16 + h) * 64 + dn + 1) * 2048 + sw] = __float2half_rn(v1);
                }
            }
        }
    }
}

__global__ void __launch_bounds__(512, 1) proj_qkv(
    const float* __restrict__ WQb, const float* __restrict__ WKb,
    const float* __restrict__ WVb)
{
    const int z = blockIdx.z;
    if (z == 0)      proj_body(g_Qh, g_Wh[0], WQb, (void*)g_q, 1);
    else if (z == 1) proj_body(g_Kh, g_Wh[1], WKb, (void*)g_k, 1);
    else             proj_body(g_Vh, g_Wh[2], WVb, (void*)g_vT, 2);
}

__global__ void __launch_bounds__(512, 1) proj_out(
    const float* __restrict__ Wob, float* __restrict__ out)
{
    proj_body(g_attnh, g_Wh[3], Wob, (void*)out, 0);
}

// ---------------------------------------------------------------------------
// Fused attention v5:
// Pass A: QK once, exp in fp32, store half2 exp to g_exph (PV a-frag layout),
//         accumulate row sums.
// Pass B: NO K staging, NO QK mma: load half exp, write P = half_exp * inv,
//         PV with raw half exp a-frags; normalize oacc in epilogue.
// ---------------------------------------------------------------------------
#define NCH2 16
#define BUFW 5120
#define FA_SMEM_BYTES (4*BUFW*4)   // 81920

__global__ void __launch_bounds__(256, 2) fused_attn(float* __restrict__ P)
{
    extern __shared__ uint32_t sm[];
    const int tid = threadIdx.x;
    const int lane = tid & 31, warp = tid >> 5;
    const int g = lane >> 2, t = lane & 3;
    const int bh = blockIdx.y;
    const int i0 = blockIdx.x * 128;
    const int b_ = bh >> 4, h = bh & 15;
    const int wm = warp * 16;
    const int row0 = i0 + wm + g;

    const uint32_t* Kg = g_k + (size_t)bh * SSEQ * 32;
    const uint32_t* Vg = g_vT + (size_t)bh * DK * 1024;
    uint32_t* Eg = g_exph + (size_t)bh * SSEQ * 1024;
    float* Pg = P + (size_t)bh * SSEQ * SSEQ;
    const uint32_t* mb0 = g_mbits + ((size_t)b_ * SSEQ + row0) * 64;
    const uint32_t* mb1 = mb0 + (size_t)8 * 64;

    const uint32_t sbase = (uint32_t)__cvta_generic_to_shared(sm);

    auto stageK_to = [&](int c, int buf) {
        const uint32_t dbase = sbase + (uint32_t)(buf * BUFW) * 4;
        const uint32_t* src = Kg + (size_t)c * 4096;
#pragma unroll
        for (int s = 0; s < 4; s++) {
            const int idx = tid + s * 256;
            const int key = idx >> 3, seg = idx & 7;
            cp16(dbase + (uint32_t)(key * 40 + seg * 4) * 4, src + key * 32 + seg * 4);
        }
    };
    auto stageV_to = [&](int c, int buf) {
        const uint32_t dbase = sbase + (uint32_t)(buf * BUFW) * 4;
#pragma unroll
        for (int s = 0; s < 4; s++) {
            const int idx = tid + s * 256;
            const int d = idx >> 4, seg = idx & 15;
            cp16(dbase + (uint32_t)(d * 72 + seg * 4) * 4,
                 Vg + (size_t)d * 1024 + c * 64 + seg * 4);
        }
    };

    uint32_t qf[4][4];
#pragma unroll
    for (int ks = 0; ks < 4; ks++) {
        const uint2 qa = *(const uint2*)&g_q[((size_t)bh * SSEQ + row0) * 32 + ks * 8 + 2 * t];
        const uint2 qb = *(const uint2*)&g_q[((size_t)bh * SSEQ + row0 + 8) * 32 + ks * 8 + 2 * t];
        qf[ks][0] = qa.x; qf[ks][2] = qa.y;
        qf[ks][1] = qb.x; qf[ks][3] = qb.y;
    }

    auto qk_half = [&](const uint32_t* Kb, int half, float cc[8][4]) {
#pragma unroll
        for (int ks = 0; ks < 4; ks++) {
            const int kb = ks * 8 + 2 * t;
#pragma unroll
            for (int nt = 0; nt < 8; nt++) {
                const uint2 kv = *(const uint2*)&Kb[(half * 64 + nt * 8 + g) * 40 + kb];
                uint32_t bb[2] = { kv.x, kv.y };
                mma_f16(cc[nt], qf[ks], bb);
            }
        }
    };

    // ================= PASS A: QK + exp + store half exp + row sums ========
    float l0 = 0.f, l1 = 0.f;
    stageK_to(0, 0); cp_commit();
    stageK_to(1, 1); cp_commit();
    stageK_to(2, 2); cp_commit();
    for (int c = 0; c < NCH2; c++) {
        if (c <= 13) cp_wait<2>();
        else if (c == 14) cp_wait<1>();
        else cp_wait<0>();
        __syncthreads();
        if (c + 3 < NCH2) { stageK_to(c + 3, (c + 3) & 3); cp_commit(); }
        const uint32_t* Kb = sm + (c & 3) * BUFW;
#pragma unroll
        for (int half = 0; half < 2; half++) {
            float cc[8][4] = {};
            qk_half(Kb, half, cc);
            uint32_t* E0 = Eg + (size_t)row0 * 1024 + c * 64 + half * 32 + t;
            uint32_t* E1 = E0 + (size_t)8 * 1024;
            const uint2 w0 = *(const uint2*)(mb0 + c * 4 + half * 2);
            const uint2 w1 = *(const uint2*)(mb1 + c * 4 + half * 2);
            if ((w0.x | w0.y | w1.x | w1.y) == 0u) {
#pragma unroll
                for (int nt = 0; nt < 8; nt++) {
                    const float e0 = exp2f(cc[nt][0] * EXPC);
                    const float e1 = exp2f(cc[nt][1] * EXPC);
                    const float e2 = exp2f(cc[nt][2] * EXPC);
                    const float e3 = exp2f(cc[nt][3] * EXPC);
                    l0 += e0 + e1; l1 += e2 + e3;
                    E0[nt * 4] = h2pack(e0, e1);
                    E1[nt * 4] = h2pack(e2, e3);
                }
            } else {
#pragma unroll
                for (int nt = 0; nt < 8; nt++) {
                    const int sh = (nt * 8) & 31;
                    const uint32_t m0w = (nt < 4) ? w0.x : w0.y;
                    const uint32_t m1w = (nt < 4) ? w1.x : w1.y;
                    const float e0 = ((m0w >> (sh + 2 * t))     & 1) ? 0.f : exp2f(cc[nt][0] * EXPC);
                    const float e1 = ((m0w >> (sh + 2 * t + 1)) & 1) ? 0.f : exp2f(cc[nt][1] * EXPC);
                    const float e2 = ((m1w >> (sh + 2 * t))     & 1) ? 0.f : exp2f(cc[nt][2] * EXPC);
                    const float e3 = ((m1w >> (sh + 2 * t + 1)) & 1) ? 0.f : exp2f(cc[nt][3] * EXPC);
                    l0 += e0 + e1; l1 += e2 + e3;
                    E0[nt * 4] = h2pack(e0, e1);
                    E1[nt * 4] = h2pack(e2, e3);
                }
            }
        }
    }
    l0 += __shfl_xor_sync(0xffffffffu, l0, 1);
    l0 += __shfl_xor_sync(0xffffffffu, l0, 2);
    l1 += __shfl_xor_sync(0xffffffffu, l1, 1);
    l1 += __shfl_xor_sync(0xffffffffu, l1, 2);
    const float inv0 = 1.f / l0, inv1 = 1.f / l1;

    __syncthreads();   // pass-A buffers quiesce before pass-B staging

    // ================= PASS B: P write + PV from stored exp ================
    float oacc[8][4] = {};
    stageV_to(0, 0); cp_commit();
    for (int c = 0; c < NCH2; c++) {
        cp_wait<0>();
        __syncthreads();
        if (c + 1 < NCH2) { stageV_to(c + 1, (c + 1) & 1); cp_commit(); }
        const uint32_t* Vb = sm + (c & 1) * BUFW;
#pragma unroll
        for (int half = 0; half < 2; half++) {
            const uint32_t* E0 = Eg + (size_t)row0 * 1024 + c * 64 + half * 32 + t;
            const uint32_t* E1 = E0 + (size_t)8 * 1024;
            uint32_t ew0[8], ew1[8];
#pragma unroll
            for (int nt = 0; nt < 8; nt++) { ew0[nt] = E0[nt * 4]; ew1[nt] = E1[nt * 4]; }
            // P output: float(half exp) * inv
            const int jc = c * 128 + half * 64;
            float* pr0 = &Pg[(size_t)row0 * SSEQ + jc + 2 * t];
            float* pr1 = &Pg[(size_t)(row0 + 8) * SSEQ + jc + 2 * t];
#pragma unroll
            for (int nt = 0; nt < 8; nt++) {
                const float2 f0 = __half22float2(*(__half2*)&ew0[nt]);
                const float2 f1 = __half22float2(*(__half2*)&ew1[nt]);
                *(float2*)&pr0[nt * 8] = make_float2(f0.x * inv0, f0.y * inv0);
                *(float2*)&pr1[nt * 8] = make_float2(f1.x * inv1, f1.y * inv1);
            }
            // PV: a-frags are the raw stored half words (unnormalized)
#pragma unroll
            for (int ks = 0; ks < 4; ks++) {
                uint32_t a[4] = { ew0[2*ks], ew1[2*ks], ew0[2*ks+1], ew1[2*ks+1] };
                const int kb = half * 32 + ks * 8 + 2 * t;
#pragma unroll
                for (int nt = 0; nt < 8; nt++) {
                    const uint2 vv = *(const uint2*)&Vb[(nt * 8 + g) * 72 + kb];
                    uint32_t bb[2] = { vv.x, vv.y };
                    mma_f16(oacc[nt], a, bb);
                }
            }
        }
    }

    // epilogue: normalize oacc, pack merged attn
#pragma unroll
    for (int nt = 0; nt < 8; nt++) {
        const int widx = (h * 4 + (nt >> 1)) * 8 + 2 * t + (nt & 1);
        g_attnh[((size_t)(b_ * SSEQ + row0)) * 512 + widx] =
            h2pack(oacc[nt][0] * inv0, oacc[nt][1] * inv0);
        g_attnh[((size_t)(b_ * SSEQ + row0 + 8)) * 512 + widx] =
            h2pack(oacc[nt][2] * inv1, oacc[nt][3] * inv1);
    }
}

// ---------------------------------------------------------------------------
extern "C" void kernel_launch(void* const* d_in, const int* in_sizes, int n_in,
                              void* d_out, int out_size)
{
    const float* Q   = (const float*)d_in[0];
    const float* K   = (const float*)d_in[1];
    const float* V   = (const float*)d_in[2];
    const unsigned char* mask = (const unsigned char*)d_in[3];
    const float* WQw = (const float*)d_in[4];
    const float* WQb = (const float*)d_in[5];
    const float* WKw = (const float*)d_in[6];
    const float* WKb = (const float*)d_in[7];
    const float* WVw = (const float*)d_in[8];
    const float* WVb = (const float*)d_in[9];
    const float* Wow = (const float*)d_in[10];
    const float* Wob = (const float*)d_in[11];

    float* out   = (float*)d_out;                       // [B,S,D]
    float* attnw = out + (size_t)MTOT * DM;             // [B,H,S,S]

    cudaFuncSetAttribute(fused_attn, cudaFuncAttributeMaxDynamicSharedMemorySize,
                         FA_SMEM_BYTES);
    cudaFuncSetAttribute(proj_qkv, cudaFuncAttributeMaxDynamicSharedMemorySize,
                         PJ_SMEM_BYTES);
    cudaFuncSetAttribute(proj_out, cudaFuncAttributeMaxDynamicSharedMemorySize,
                         PJ_SMEM_BYTES);

    pack_all<<<5120, 256>>>(Q, K, V, WQw, WKw, WVw, Wow, mask);

    proj_qkv<<<dim3(8, 16, 3), 512, PJ_SMEM_BYTES>>>(WQb, WKb, WVb);

    fused_attn<<<dim3(16, 32), 256, FA_SMEM_BYTES>>>(attnw);

    proj_out<<<dim3(8, 16), 512, PJ_SMEM_BYTES>>>(Wob, out);
}